// round 4
// baseline (speedup 1.0000x reference)
#include <cuda_runtime.h>
#include <cuda_fp16.h>
#include <cstdint>

// ============================================================================
// Problem constants
// ============================================================================
#define IN_DIM   4096
#define OUT_DIM  4096
#define MROWS    8192        // BSZ * SEQ
#define TRANK    64
#define LORA_SCALE 2.0f      // alpha/r = 32/16 for every adapter

// GEMM tiling: CTA 128x256, BK=32, 8-stage cp.async pipeline, pair-unrolled
#define BM 128
#define BN 256
#define BK 32
#define KT (IN_DIM / BK)          // 128 k-tiles
#define NPAIRS (KT / 2)           // 64
#define STAGES 8
#define A_BYTES (BM * BK * 2)     // 8192
#define B_BYTES (BN * BK * 2)     // 16384
#define STAGE_BYTES (A_BYTES + B_BYTES)   // 24576
#define SMEM_TOTAL (STAGES * STAGE_BYTES) // 196608

// ============================================================================
// Device scratch (allocation-free rule: __device__ globals)
// ============================================================================
__device__ __half d_Xh[(size_t)MROWS * IN_DIM];    // 64 MiB
__device__ __half d_Wh[(size_t)OUT_DIM * IN_DIM];  // 32 MiB

// ============================================================================
// PTX helpers
// ============================================================================
__device__ __forceinline__ uint32_t smem_u32(const void* p) {
    uint32_t a;
    asm("{ .reg .u64 t; cvta.to.shared.u64 t, %1; cvt.u32.u64 %0, t; }"
        : "=r"(a) : "l"(p));
    return a;
}

#define CP_ASYNC16(dst, src) \
    asm volatile("cp.async.cg.shared.global [%0], [%1], 16;" \
                 :: "r"(dst), "l"(src) : "memory")
#define CP_COMMIT() asm volatile("cp.async.commit_group;" ::: "memory")
#define CP_WAIT2()  asm volatile("cp.async.wait_group 2;" ::: "memory")

__device__ __forceinline__ void ldmatrix_x4(uint32_t& r0, uint32_t& r1,
                                            uint32_t& r2, uint32_t& r3,
                                            uint32_t addr) {
    asm volatile("ldmatrix.sync.aligned.m8n8.x4.shared.b16 {%0,%1,%2,%3}, [%4];"
                 : "=r"(r0), "=r"(r1), "=r"(r2), "=r"(r3) : "r"(addr));
}
__device__ __forceinline__ void ldmatrix_x2(uint32_t& r0, uint32_t& r1,
                                            uint32_t addr) {
    asm volatile("ldmatrix.sync.aligned.m8n8.x2.shared.b16 {%0,%1}, [%2];"
                 : "=r"(r0), "=r"(r1) : "r"(addr));
}
__device__ __forceinline__ void mma16816(float* c, const uint32_t* a,
                                         const uint32_t* b) {
    asm volatile(
        "mma.sync.aligned.m16n8k16.row.col.f32.f16.f16.f32 "
        "{%0,%1,%2,%3}, {%4,%5,%6,%7}, {%8,%9}, {%0,%1,%2,%3};"
        : "+f"(c[0]), "+f"(c[1]), "+f"(c[2]), "+f"(c[3])
        : "r"(a[0]), "r"(a[1]), "r"(a[2]), "r"(a[3]), "r"(b[0]), "r"(b[1]));
}

// Swizzle for 64-byte rows, 16B chunks: phys_chunk = chunk ^ ((row>>1)&3)
__device__ __forceinline__ uint32_t sw_off(int row, int chunk) {
    return (uint32_t)(row * 64 + ((chunk ^ ((row >> 1) & 3)) << 4));
}

// ============================================================================
// Prologue 1: x (fp32) -> d_Xh (fp16, RN)
// ============================================================================
__global__ void cvt_x_kernel(const float4* __restrict__ x) {
    const int n8 = (MROWS * IN_DIM) / 8;
    for (int i = blockIdx.x * blockDim.x + threadIdx.x; i < n8;
         i += gridDim.x * blockDim.x) {
        float4 a = x[2 * i];
        float4 b = x[2 * i + 1];
        __half2 h0 = __floats2half2_rn(a.x, a.y);
        __half2 h1 = __floats2half2_rn(a.z, a.w);
        __half2 h2 = __floats2half2_rn(b.x, b.y);
        __half2 h3 = __floats2half2_rn(b.z, b.w);
        uint4 v;
        v.x = *reinterpret_cast<uint32_t*>(&h0);
        v.y = *reinterpret_cast<uint32_t*>(&h1);
        v.z = *reinterpret_cast<uint32_t*>(&h2);
        v.w = *reinterpret_cast<uint32_t*>(&h3);
        reinterpret_cast<uint4*>(d_Xh)[i] = v;
    }
}

// ============================================================================
// Prologue 2: W_eff = W + 2 * B @ A  -> d_Wh (fp16)
// ============================================================================
__global__ void build_weff_kernel(const float* __restrict__ W,
                                  const float* __restrict__ A,   // [64, 4096]
                                  const float* __restrict__ B) { // [4096, 64]
    __shared__ float sA[64][65];
    __shared__ float sB[64][65];
    const int tid = threadIdx.x;
    const int n0 = blockIdx.y * 64;
    const int k0 = blockIdx.x * 64;

    for (int t = tid; t < 64 * 64; t += 256) {
        int i = t >> 6, c = t & 63;
        sA[i][c] = A[i * IN_DIM + k0 + c];
        sB[i][c] = LORA_SCALE * B[(size_t)(n0 + i) * TRANK + c];
    }
    __syncthreads();

    const int tj = tid & 15, ti = tid >> 4;
    float acc[4][4] = {};
#pragma unroll 8
    for (int r = 0; r < 64; r++) {
        float bv[4], av[4];
#pragma unroll
        for (int q = 0; q < 4; q++) { bv[q] = sB[ti * 4 + q][r]; av[q] = sA[r][tj * 4 + q]; }
#pragma unroll
        for (int p = 0; p < 4; p++)
#pragma unroll
            for (int q = 0; q < 4; q++) acc[p][q] += bv[p] * av[q];
    }
#pragma unroll
    for (int p = 0; p < 4; p++) {
        int n = n0 + ti * 4 + p;
#pragma unroll
        for (int q = 0; q < 4; q++) {
            int k = k0 + tj * 4 + q;
            d_Wh[(size_t)n * IN_DIM + k] =
                __float2half_rn(W[(size_t)n * IN_DIM + k] + acc[p][q]);
        }
    }
}

// ============================================================================
// Main GEMM: out[8192,4096] = Xh @ Whᵀ  (fp16 in, fp32 accum, mma.sync)
// CTA 128x256, 512 threads, 16 warps (2m x 8n), warp tile 64x32.
// 8-stage pipeline; ONE wait+barrier per 2 k-tiles; prefetch 3 pairs deep.
// ============================================================================
__global__ void __launch_bounds__(512, 1) lora_gemm_kernel(float* __restrict__ out) {
    extern __shared__ __align__(1024) char smem[];
    const uint32_t sb = smem_u32(smem);
    const int tid = threadIdx.x;
    const int wid = tid >> 5, lane = tid & 31;
    const int warp_m = wid & 1;          // 0..1  (64 rows each)
    const int warp_n = wid >> 1;         // 0..7  (32 cols each)

    const int mbase = blockIdx.x * BM;
    const int nbase = blockIdx.y * BN;

    const __half* gX = d_Xh;
    const __half* gW = d_Wh;

    // ---- cp.async loader pattern: 512 threads, 16B chunks ----
    // A: 128 rows x 4 chunks = 512 chunks (1/thread)
    // B: 256 rows x 4 chunks = 1024 chunks (2/thread)
    const int ld_row = tid >> 2;          // 0..127
    const int ld_c   = tid & 3;           // 0..3

    auto issue_stage = [&](int kt, int s) {
        const uint32_t base = sb + s * STAGE_BYTES;
        const size_t gk = (size_t)kt * BK + ld_c * 8;
        CP_ASYNC16(base + sw_off(ld_row, ld_c),
                   gX + (size_t)(mbase + ld_row) * IN_DIM + gk);
#pragma unroll
        for (int p = 0; p < 2; p++) {
            const int row = ld_row + p * 128;
            CP_ASYNC16(base + A_BYTES + sw_off(row, ld_c),
                       gW + (size_t)(nbase + row) * IN_DIM + gk);
        }
    };

    // ---- prologue: 3 pairs (6 stages) in flight ----
#pragma unroll
    for (int g = 0; g < 3; g++) {
        issue_stage(2 * g,     (2 * g) & (STAGES - 1));
        issue_stage(2 * g + 1, (2 * g + 1) & (STAGES - 1));
        CP_COMMIT();
    }

    // ---- ldmatrix lane addressing ----
    const int a_row_l = warp_m * 64 + (lane & 15);
    const int a_cgrp  = lane >> 4;          // 0..1
    const int b_row_l = warp_n * 32 + (lane & 7);
    const int b_cgrp  = (lane >> 3) & 1;

    float acc[4][4][4] = {};   // [mt][nt][frag]

    for (int p = 0; p < NPAIRS; p++) {
        CP_WAIT2();          // pair p's group complete (own view)
        __syncthreads();     // visibility + all warps done reading pair p-1 slots

        // prefetch pair p+3 into the slots read at pair p-1 (safe post-barrier)
        if (p + 3 < NPAIRS) {
            const int kt0 = 2 * (p + 3);
            issue_stage(kt0,     kt0 & (STAGES - 1));
            issue_stage(kt0 + 1, (kt0 + 1) & (STAGES - 1));
        }
        CP_COMMIT();

        // compute the two k-tiles of pair p
#pragma unroll
        for (int half = 0; half < 2; half++) {
            const int kt = 2 * p + half;
            const uint32_t abase = sb + (kt & (STAGES - 1)) * STAGE_BYTES;
            const uint32_t bbase = abase + A_BYTES;
#pragma unroll
            for (int ks = 0; ks < 2; ks++) {
                uint32_t af[4][4];
                uint32_t bf[4][2];
#pragma unroll
                for (int mt = 0; mt < 4; mt++) {
                    const int row = a_row_l + mt * 16;
                    ldmatrix_x4(af[mt][0], af[mt][1], af[mt][2], af[mt][3],
                                abase + sw_off(row, ks * 2 + a_cgrp));
                }
#pragma unroll
                for (int nt = 0; nt < 4; nt++) {
                    const int row = b_row_l + nt * 8;
                    ldmatrix_x2(bf[nt][0], bf[nt][1],
                                bbase + sw_off(row, ks * 2 + b_cgrp));
                }
#pragma unroll
                for (int mt = 0; mt < 4; mt++)
#pragma unroll
                    for (int nt = 0; nt < 4; nt++)
                        mma16816(acc[mt][nt], af[mt], bf[nt]);
            }
        }
    }

    // ---- epilogue: registers -> gmem ----
    const int er = lane >> 2;            // 0..7
    const int ec = (lane & 3) * 2;       // 0,2,4,6
#pragma unroll
    for (int mt = 0; mt < 4; mt++) {
#pragma unroll
        for (int nt = 0; nt < 4; nt++) {
            const int r0 = mbase + warp_m * 64 + mt * 16 + er;
            const int c0 = nbase + warp_n * 32 + nt * 8 + ec;
            float2 v0 = make_float2(acc[mt][nt][0], acc[mt][nt][1]);
            float2 v1 = make_float2(acc[mt][nt][2], acc[mt][nt][3]);
            *reinterpret_cast<float2*>(out + (size_t)r0 * OUT_DIM + c0) = v0;
            *reinterpret_cast<float2*>(out + (size_t)(r0 + 8) * OUT_DIM + c0) = v1;
        }
    }
}

// ============================================================================
// Host side
// ============================================================================
extern "C" void kernel_launch(void* const* d_in, const int* in_sizes, int n_in,
                              void* d_out, int out_size) {
    (void)in_sizes; (void)n_in; (void)out_size;
    const float* x  = (const float*)d_in[0];
    const float* w  = (const float*)d_in[1];
    const float* la = (const float*)d_in[2];
    const float* lb = (const float*)d_in[3];
    float* out = (float*)d_out;

    cvt_x_kernel<<<4096, 256>>>(reinterpret_cast<const float4*>(x));
    build_weff_kernel<<<dim3(IN_DIM / 64, OUT_DIM / 64), 256>>>(w, la, lb);

    cudaFuncSetAttribute(lora_gemm_kernel,
                         cudaFuncAttributeMaxDynamicSharedMemorySize, SMEM_TOTAL);
    lora_gemm_kernel<<<dim3(MROWS / BM, OUT_DIM / BN), 512, SMEM_TOTAL>>>(out);
}

// round 5
// speedup vs baseline: 1.6944x; 1.6944x over previous
#include <cuda_runtime.h>
#include <cuda_fp16.h>
#include <cstdint>

// ============================================================================
// Problem constants
// ============================================================================
#define IN_DIM   4096
#define OUT_DIM  4096
#define MROWS    8192        // BSZ * SEQ
#define TRANK    64
#define LORA_SCALE 2.0f      // alpha/r = 32/16 for every adapter

// GEMM tiling (sm_103 base target: mma.sync + ldmatrix + cp.async)
// 128x128 CTA, 256 threads, 2 CTAs/SM (load-bearing!), 5-stage pipeline.
#define BM 128
#define BN 128
#define BK 32
#define KT (IN_DIM / BK)          // 128 k-tiles
#define STAGES 5
#define A_BYTES (BM * BK * 2)     // 8192
#define B_BYTES (BN * BK * 2)     // 8192
#define STAGE_BYTES (A_BYTES + B_BYTES)   // 16384
#define SMEM_TOTAL (STAGES * STAGE_BYTES) // 81920  (x2 CTAs = 160KB <= 228KB)

// grid rasterization: group 8 m-tiles per n-panel for L2/DRAM reuse
#define NUM_PID_M (MROWS / BM)    // 64
#define NUM_PID_N (OUT_DIM / BN)  // 32
#define GRPM 8

// ============================================================================
// Device scratch (allocation-free rule: __device__ globals)
// ============================================================================
__device__ __half d_Xh[(size_t)MROWS * IN_DIM];    // 64 MiB
__device__ __half d_Wh[(size_t)OUT_DIM * IN_DIM];  // 32 MiB

// ============================================================================
// PTX helpers
// ============================================================================
__device__ __forceinline__ uint32_t smem_u32(const void* p) {
    uint32_t a;
    asm("{ .reg .u64 t; cvta.to.shared.u64 t, %1; cvt.u32.u64 %0, t; }"
        : "=r"(a) : "l"(p));
    return a;
}

#define CP_ASYNC16(dst, src) \
    asm volatile("cp.async.cg.shared.global [%0], [%1], 16;" \
                 :: "r"(dst), "l"(src) : "memory")
#define CP_COMMIT() asm volatile("cp.async.commit_group;" ::: "memory")
#define CP_WAIT3()  asm volatile("cp.async.wait_group 3;" ::: "memory")

__device__ __forceinline__ void ldmatrix_x4(uint32_t& r0, uint32_t& r1,
                                            uint32_t& r2, uint32_t& r3,
                                            uint32_t addr) {
    asm volatile("ldmatrix.sync.aligned.m8n8.x4.shared.b16 {%0,%1,%2,%3}, [%4];"
                 : "=r"(r0), "=r"(r1), "=r"(r2), "=r"(r3) : "r"(addr));
}
__device__ __forceinline__ void ldmatrix_x2(uint32_t& r0, uint32_t& r1,
                                            uint32_t addr) {
    asm volatile("ldmatrix.sync.aligned.m8n8.x2.shared.b16 {%0,%1}, [%2];"
                 : "=r"(r0), "=r"(r1) : "r"(addr));
}
__device__ __forceinline__ void mma16816(float* c, const uint32_t* a,
                                         const uint32_t* b) {
    asm volatile(
        "mma.sync.aligned.m16n8k16.row.col.f32.f16.f16.f32 "
        "{%0,%1,%2,%3}, {%4,%5,%6,%7}, {%8,%9}, {%0,%1,%2,%3};"
        : "+f"(c[0]), "+f"(c[1]), "+f"(c[2]), "+f"(c[3])
        : "r"(a[0]), "r"(a[1]), "r"(a[2]), "r"(a[3]), "r"(b[0]), "r"(b[1]));
}

// Swizzle for 64-byte rows, 16B chunks: phys_chunk = chunk ^ ((row>>1)&3)
__device__ __forceinline__ uint32_t sw_off(int row, int chunk) {
    return (uint32_t)(row * 64 + ((chunk ^ ((row >> 1) & 3)) << 4));
}

// ============================================================================
// Prologue 1: x (fp32) -> d_Xh (fp16, RN)
// ============================================================================
__global__ void cvt_x_kernel(const float4* __restrict__ x) {
    const int n8 = (MROWS * IN_DIM) / 8;
    for (int i = blockIdx.x * blockDim.x + threadIdx.x; i < n8;
         i += gridDim.x * blockDim.x) {
        float4 a = x[2 * i];
        float4 b = x[2 * i + 1];
        __half2 h0 = __floats2half2_rn(a.x, a.y);
        __half2 h1 = __floats2half2_rn(a.z, a.w);
        __half2 h2 = __floats2half2_rn(b.x, b.y);
        __half2 h3 = __floats2half2_rn(b.z, b.w);
        uint4 v;
        v.x = *reinterpret_cast<uint32_t*>(&h0);
        v.y = *reinterpret_cast<uint32_t*>(&h1);
        v.z = *reinterpret_cast<uint32_t*>(&h2);
        v.w = *reinterpret_cast<uint32_t*>(&h3);
        reinterpret_cast<uint4*>(d_Xh)[i] = v;
    }
}

// ============================================================================
// Prologue 2: W_eff = W + 2 * B @ A  -> d_Wh (fp16)
// ============================================================================
__global__ void build_weff_kernel(const float* __restrict__ W,
                                  const float* __restrict__ A,   // [64, 4096]
                                  const float* __restrict__ B) { // [4096, 64]
    __shared__ float sA[64][65];
    __shared__ float sB[64][65];
    const int tid = threadIdx.x;
    const int n0 = blockIdx.y * 64;
    const int k0 = blockIdx.x * 64;

    for (int t = tid; t < 64 * 64; t += 256) {
        int i = t >> 6, c = t & 63;
        sA[i][c] = A[i * IN_DIM + k0 + c];
        sB[i][c] = LORA_SCALE * B[(size_t)(n0 + i) * TRANK + c];
    }
    __syncthreads();

    const int tj = tid & 15, ti = tid >> 4;
    float acc[4][4] = {};
#pragma unroll 8
    for (int r = 0; r < 64; r++) {
        float bv[4], av[4];
#pragma unroll
        for (int q = 0; q < 4; q++) { bv[q] = sB[ti * 4 + q][r]; av[q] = sA[r][tj * 4 + q]; }
#pragma unroll
        for (int p = 0; p < 4; p++)
#pragma unroll
            for (int q = 0; q < 4; q++) acc[p][q] += bv[p] * av[q];
    }
#pragma unroll
    for (int p = 0; p < 4; p++) {
        int n = n0 + ti * 4 + p;
#pragma unroll
        for (int q = 0; q < 4; q++) {
            int k = k0 + tj * 4 + q;
            d_Wh[(size_t)n * IN_DIM + k] =
                __float2half_rn(W[(size_t)n * IN_DIM + k] + acc[p][q]);
        }
    }
}

// ============================================================================
// Main GEMM: out[8192,4096] = Xh @ Whᵀ  (fp16 in, fp32 accum, mma.sync)
// CTA 128x128, 8 warps (2m x 4n), warp tile 64x32, 5-stage cp.async pipeline.
// 1D grid + grouped rasterization (GRPM m-tiles share an n-panel in L2).
// ============================================================================
__global__ void __launch_bounds__(256, 2) lora_gemm_kernel(float* __restrict__ out) {
    extern __shared__ __align__(1024) char smem[];
    const uint32_t sb = smem_u32(smem);
    const int tid = threadIdx.x;
    const int wid = tid >> 5, lane = tid & 31;
    const int warp_m = wid & 1;          // 0..1  (64 rows each)
    const int warp_n = wid >> 1;         // 0..3  (32 cols each)

    // ---- grouped rasterization ----
    const int pid = blockIdx.x;
    const int group_size = GRPM * NUM_PID_N;
    const int group_id = pid / group_size;
    const int pid_in = pid - group_id * group_size;
    const int pid_m = group_id * GRPM + (pid_in % GRPM);
    const int pid_n = pid_in / GRPM;

    const int mbase = pid_m * BM;
    const int nbase = pid_n * BN;

    const __half* gX = d_Xh;
    const __half* gW = d_Wh;

    // ---- cp.async loader pattern: 256 threads, 16B chunks, 2 rows-passes ----
    const int ld_row = tid >> 2;          // 0..63
    const int ld_c   = tid & 3;           // 0..3

    auto issue_stage = [&](int kt, int s) {
        const uint32_t base = sb + s * STAGE_BYTES;
        const size_t gk = (size_t)kt * BK + ld_c * 8;
#pragma unroll
        for (int p = 0; p < 2; p++) {
            const int row = ld_row + p * 64;
            const uint32_t off = sw_off(row, ld_c);
            CP_ASYNC16(base + off,
                       gX + (size_t)(mbase + row) * IN_DIM + gk);
            CP_ASYNC16(base + A_BYTES + off,
                       gW + (size_t)(nbase + row) * IN_DIM + gk);
        }
    };

    // ---- prologue: fill 4 stages ----
#pragma unroll
    for (int i = 0; i < STAGES - 1; i++) {
        issue_stage(i, i);
        CP_COMMIT();
    }

    // ---- ldmatrix lane addressing ----
    const int a_row_l = warp_m * 64 + (lane & 15);
    const int a_cgrp  = lane >> 4;          // 0..1
    const int b_row_l = warp_n * 32 + (lane & 7);
    const int b_cgrp  = (lane >> 3) & 1;

    float acc[4][4][4] = {};   // [mt][nt][frag]

    int s = 0;
    for (int kt = 0; kt < KT; kt++) {
        CP_WAIT3();          // stage kt's group complete (own view)
        __syncthreads();     // visibility + all warps done with stage kt-1's slot

        // prefetch stage kt+4 into the slot read at iteration kt-1
        const int ktn = kt + STAGES - 1;
        if (ktn < KT) {
            int sn = s + STAGES - 1;
            if (sn >= STAGES) sn -= STAGES;
            issue_stage(ktn, sn);
        }
        CP_COMMIT();

        const uint32_t abase = sb + s * STAGE_BYTES;
        const uint32_t bbase = abase + A_BYTES;

#pragma unroll
        for (int ks = 0; ks < 2; ks++) {
            uint32_t af[4][4];
            uint32_t bf[4][2];
#pragma unroll
            for (int mt = 0; mt < 4; mt++) {
                const int row = a_row_l + mt * 16;
                ldmatrix_x4(af[mt][0], af[mt][1], af[mt][2], af[mt][3],
                            abase + sw_off(row, ks * 2 + a_cgrp));
            }
#pragma unroll
            for (int nt = 0; nt < 4; nt++) {
                const int row = b_row_l + nt * 8;
                ldmatrix_x2(bf[nt][0], bf[nt][1],
                            bbase + sw_off(row, ks * 2 + b_cgrp));
            }
#pragma unroll
            for (int mt = 0; mt < 4; mt++)
#pragma unroll
                for (int nt = 0; nt < 4; nt++)
                    mma16816(acc[mt][nt], af[mt], bf[nt]);
        }

        if (++s == STAGES) s = 0;
    }

    // ---- epilogue: registers -> gmem ----
    const int er = lane >> 2;            // 0..7
    const int ec = (lane & 3) * 2;       // 0,2,4,6
#pragma unroll
    for (int mt = 0; mt < 4; mt++) {
#pragma unroll
        for (int nt = 0; nt < 4; nt++) {
            const int r0 = mbase + warp_m * 64 + mt * 16 + er;
            const int c0 = nbase + warp_n * 32 + nt * 8 + ec;
            float2 v0 = make_float2(acc[mt][nt][0], acc[mt][nt][1]);
            float2 v1 = make_float2(acc[mt][nt][2], acc[mt][nt][3]);
            *reinterpret_cast<float2*>(out + (size_t)r0 * OUT_DIM + c0) = v0;
            *reinterpret_cast<float2*>(out + (size_t)(r0 + 8) * OUT_DIM + c0) = v1;
        }
    }
}

// ============================================================================
// Host side
// ============================================================================
extern "C" void kernel_launch(void* const* d_in, const int* in_sizes, int n_in,
                              void* d_out, int out_size) {
    (void)in_sizes; (void)n_in; (void)out_size;
    const float* x  = (const float*)d_in[0];
    const float* w  = (const float*)d_in[1];
    const float* la = (const float*)d_in[2];
    const float* lb = (const float*)d_in[3];
    float* out = (float*)d_out;

    cvt_x_kernel<<<4096, 256>>>(reinterpret_cast<const float4*>(x));
    build_weff_kernel<<<dim3(IN_DIM / 64, OUT_DIM / 64), 256>>>(w, la, lb);

    cudaFuncSetAttribute(lora_gemm_kernel,
                         cudaFuncAttributeMaxDynamicSharedMemorySize, SMEM_TOTAL);
    lora_gemm_kernel<<<NUM_PID_M * NUM_PID_N, 256, SMEM_TOTAL>>>(out);
}